// round 8
// baseline (speedup 1.0000x reference)
#include <cuda_runtime.h>
#include <cuda_fp16.h>
#include <stdint.h>

#define M_ROWS 16384
#define N_CODES 8192
#define KDIM 256
#define Q_ELEMS (M_ROWS * KDIM)

// ---------------- tcgen05 path config ----------------
#define TC_MT 256
#define TC_NT 256
#define TC_CK 32                 // k-halves per chunk; row = [hi 32h | lo 32h] = 128B
#define TC_STAGES 3
#define TC_CHUNKS 8              // 256 / 32 (all 3 passes done per chunk)
#define TC_STAGE_BYTES 65536     // A 32KB (zh|zl) + B 32KB (eh|el)
#define TC_MBAR_OFF 64
#define TC_EN_OFF 1024
#define TC_STAGE0 2048
#define TC_TOTAL (TC_STAGE0 + TC_STAGES * TC_STAGE_BYTES)  // 198656

// ---------------- fallback path config (compile-only on PTX pass) ----------------
#define FB_MT 128
#define FB_NT 128
#define FB_STAGES 4
#define FB_CHUNKS 24
#define FB_LDAB 80
#define FB_A_TILE (FB_MT * FB_LDAB)
#define FB_B_TILE (FB_NT * FB_LDAB)
#define FB_STAGE_BYTES (FB_A_TILE + FB_B_TILE)
#define FB_EN 0
#define FB_STAGE0 512
#define FB_TOTAL (FB_STAGE0 + FB_STAGES * FB_STAGE_BYTES)

#define SMEM_LAUNCH (TC_TOTAL > FB_TOTAL ? TC_TOTAL : FB_TOTAL)

// ---------------- persistent scratch ----------------
__device__ unsigned long long g_best[M_ROWS];
__device__ float g_partial[M_ROWS];
__device__ float g_enorm[N_CODES];
__device__ __half g_zh[M_ROWS * KDIM];
__device__ __half g_zl[M_ROWS * KDIM];
__device__ __half g_eh[N_CODES * KDIM];
__device__ __half g_el[N_CODES * KDIM];

// ---------------- common helpers ----------------
__device__ __forceinline__ uint32_t smem_u32(const void* p) {
    uint32_t a;
    asm("{ .reg .u64 t; cvta.to.shared.u64 t, %1; cvt.u32.u64 %0, t; }"
        : "=r"(a) : "l"(p));
    return a;
}
__device__ __forceinline__ void cp16(uint32_t dst, const void* src) {
    asm volatile("cp.async.cg.shared.global [%0], [%1], 16;" :: "r"(dst), "l"(src));
}
__device__ __forceinline__ void cp_commit() { asm volatile("cp.async.commit_group;"); }
__device__ __forceinline__ void cp_wait2() { asm volatile("cp.async.wait_group 2;" ::: "memory"); }
__device__ __forceinline__ void cp_wait1() { asm volatile("cp.async.wait_group 1;" ::: "memory"); }
__device__ __forceinline__ void cp_wait0() { asm volatile("cp.async.wait_group 0;" ::: "memory"); }

__device__ __forceinline__ unsigned fkey(float f) {
    unsigned u = __float_as_uint(f);
    return (u & 0x80000000u) ? ~u : (u | 0x80000000u);
}
__device__ __forceinline__ unsigned long long umin64(unsigned long long a,
                                                     unsigned long long b) {
    return a < b ? a : b;
}

// ---------------- tcgen05 helpers (sm_103a cubin pass only) ----------------
#if defined(__CUDA_ARCH_FEAT_SM103_ALL)

__device__ __forceinline__ uint32_t elect_one() {
    uint32_t pred;
    asm volatile(
        "{\n\t.reg .pred p;\n\telect.sync _|p, 0xFFFFFFFF;\n\t"
        "selp.b32 %0, 1, 0, p;\n\t}" : "=r"(pred));
    return pred;
}

#define MBARRIER_INIT(addr, cnt) \
    asm volatile("mbarrier.init.shared.b64 [%0], %1;" :: "r"(addr), "r"(cnt) : "memory")

#define MBARRIER_WAIT_PARITY(mbar, parity) do {                                   \
    uint32_t _m = (mbar); uint32_t _p = (parity); uint32_t _done;                 \
    asm volatile("{\n\t.reg .pred p;\n\t"                                         \
        "mbarrier.try_wait.parity.acquire.cta.shared::cta.b64 p, [%1], %2;\n\t"   \
        "selp.b32 %0, 1, 0, p;\n\t}" : "=r"(_done) : "r"(_m), "r"(_p) : "memory");\
    if (!_done) {                                                                 \
        asm volatile("{\n\t.reg .pred P1;\n\t"                                    \
            "WAIT_LOOP_%=:\n\t"                                                   \
            "mbarrier.try_wait.parity.acquire.cta.shared::cta.b64 P1, [%0], %1, 0x989680;\n\t" \
            "@P1 bra.uni WAIT_DONE_%=;\n\t"                                       \
            "bra.uni WAIT_LOOP_%=;\n\t"                                           \
            "WAIT_DONE_%=:\n\t}" :: "r"(_m), "r"(_p) : "memory");                 \
    }                                                                             \
} while (0)

#define TCGEN05_ALLOC(smem_dst, ncols) \
    asm volatile("tcgen05.alloc.cta_group::1.sync.aligned.shared::cta.b32 [%0], %1;" \
                 :: "r"(smem_dst), "r"(ncols) : "memory")
#define TCGEN05_DEALLOC(tmem, ncols) \
    asm volatile("tcgen05.dealloc.cta_group::1.sync.aligned.b32 %0, %1;" :: "r"(tmem), "r"(ncols))
#define TCGEN05_RELINQUISH() \
    asm volatile("tcgen05.relinquish_alloc_permit.cta_group::1.sync.aligned;")
#define TCGEN05_COMMIT(mbar) \
    asm volatile("tcgen05.commit.cta_group::1.mbarrier::arrive::one.shared::cluster.b64 [%0];" \
                 :: "r"(mbar) : "memory")
#define TCGEN05_FENCE_AFTER() asm volatile("tcgen05.fence::after_thread_sync;" ::: "memory")
#define TCGEN05_FENCE_BEFORE() asm volatile("tcgen05.fence::before_thread_sync;" ::: "memory")
#define TCGEN05_WAIT_LD() asm volatile("tcgen05.wait::ld.sync.aligned;" ::: "memory")

#define TCGEN05_LD_32X32B_X32(r, tmem_addr) \
    asm volatile( \
        "tcgen05.ld.sync.aligned.32x32b.x32.b32 " \
        "{%0, %1, %2, %3, %4, %5, %6, %7, " \
        " %8, %9, %10, %11, %12, %13, %14, %15, " \
        " %16, %17, %18, %19, %20, %21, %22, %23, " \
        " %24, %25, %26, %27, %28, %29, %30, %31}, [%32];" \
        : "=r"((r)[0]),  "=r"((r)[1]),  "=r"((r)[2]),  "=r"((r)[3]), \
          "=r"((r)[4]),  "=r"((r)[5]),  "=r"((r)[6]),  "=r"((r)[7]), \
          "=r"((r)[8]),  "=r"((r)[9]),  "=r"((r)[10]), "=r"((r)[11]), \
          "=r"((r)[12]), "=r"((r)[13]), "=r"((r)[14]), "=r"((r)[15]), \
          "=r"((r)[16]), "=r"((r)[17]), "=r"((r)[18]), "=r"((r)[19]), \
          "=r"((r)[20]), "=r"((r)[21]), "=r"((r)[22]), "=r"((r)[23]), \
          "=r"((r)[24]), "=r"((r)[25]), "=r"((r)[26]), "=r"((r)[27]), \
          "=r"((r)[28]), "=r"((r)[29]), "=r"((r)[30]), "=r"((r)[31]) \
        : "r"(tmem_addr))

// SW128 descriptor: version=1, LBO=1, SBO=64 (128B rows, 8x128B atom)
static __device__ __forceinline__ unsigned long long make_desc(uint32_t addr) {
    const unsigned long long base =
        (2ull << 61) | (1ull << 46) | (64ull << 32) | (1ull << 16);
    return base | ((unsigned long long)(addr >> 4) & 0x3FFFull);
}

// idesc: D=F32(1@4), A=FP16(0@7), B=FP16(0@10), N/8@17, M/16@24 (M=128 per MMA)
#define TC_IDESC ((1u << 4) | ((TC_NT / 8) << 17) | (8u << 24))

__device__ __forceinline__ void mma_f16_ss(uint32_t d, unsigned long long ad,
                                           unsigned long long bd, uint32_t en) {
    asm volatile(
        "{\n\t.reg .pred p;\n\t"
        "setp.ne.u32 p, %5, 0;\n\t"
        "tcgen05.mma.cta_group::1.kind::f16 [%0], %1, %2, %3, {%4, %4, %4, %4}, p;\n\t}"
        :: "r"(d), "l"(ad), "l"(bd), "r"((uint32_t)TC_IDESC), "r"(0u), "r"(en)
        : "memory");
}

#endif  // __CUDA_ARCH_FEAT_SM103_ALL

// ---------------- prep kernels ----------------
__global__ void split_z_kernel(const float* __restrict__ src) {
    int gid = blockIdx.x * 256 + threadIdx.x;
    float2 v = ((const float2*)src)[gid];
    __half h0 = __float2half(v.x);
    __half l0 = __float2half(v.x - __half2float(h0));
    __half h1 = __float2half(v.y);
    __half l1 = __float2half(v.y - __half2float(h1));
    *(__half2*)(g_zh + 2 * gid) = __halves2half2(h0, h1);
    *(__half2*)(g_zl + 2 * gid) = __halves2half2(l0, l1);
    if (gid < M_ROWS) g_best[gid] = ~0ull;
}

__global__ void split_e_kernel(const float* __restrict__ src) {
    int gid = blockIdx.x * 256 + threadIdx.x;
    float2 v = ((const float2*)src)[gid];
    __half h0 = __float2half(v.x);
    __half l0 = __float2half(v.x - __half2float(h0));
    __half h1 = __float2half(v.y);
    __half l1 = __float2half(v.y - __half2float(h1));
    *(__half2*)(g_eh + 2 * gid) = __halves2half2(h0, h1);
    *(__half2*)(g_el + 2 * gid) = __halves2half2(l0, l1);
}

__global__ void enorm_kernel(const float* __restrict__ emb) {
    int row = blockIdx.x * (blockDim.x >> 5) + (threadIdx.x >> 5);
    int lane = threadIdx.x & 31;
    if (row >= N_CODES) return;
    const float* e = emb + (size_t)row * KDIM;
    float s = 0.f;
#pragma unroll
    for (int c = lane; c < KDIM; c += 32) {
        float v = e[c];
        s = fmaf(v, v, s);
    }
#pragma unroll
    for (int o = 16; o; o >>= 1) s += __shfl_xor_sync(0xffffffffu, s, o);
    if (lane == 0) g_enorm[row] = s;
}

// ---------------- GEMM + argmin (dual body; cubin pass runs tcgen05) ----------------
__global__ void __launch_bounds__(256, 1) vq_gemm_kernel() {
    extern __shared__ __align__(1024) char smem[];
    const int tid = threadIdx.x;

#if defined(__CUDA_ARCH_FEAT_SM103_ALL)
    // ===== tcgen05 fp16 path: 256x256 tile; k-outer packed rows [hi|lo] =====
    const int bm = blockIdx.y * TC_MT;
    const int bn = blockIdx.x * TC_NT;
    const uint32_t sb = smem_u32(smem);

    if (tid < 32) {
        TCGEN05_ALLOC(sb, 512);
        TCGEN05_RELINQUISH();
    }
    if (tid == 0) {
        MBARRIER_INIT(sb + TC_MBAR_OFF + 0, 1);
        MBARRIER_INIT(sb + TC_MBAR_OFF + 8, 1);
        MBARRIER_INIT(sb + TC_MBAR_OFF + 16, 1);
    }
    ((float*)(smem + TC_EN_OFF))[tid] = g_enorm[bn + tid];
    __syncthreads();

    uint32_t tmem_base;
    asm volatile("ld.shared.b32 %0, [%1];" : "=r"(tmem_base) : "r"(sb));

    // this thread's fixed 16B-column within every row: ch in 0..7
    // ch<4 -> hi source (k halves k0 + ch*8), ch>=4 -> lo source (k0 + (ch-4)*8)
    const int ch = tid & 7;
    const __half* asel = (ch < 4) ? g_zh : g_zl;
    const __half* bsel = (ch < 4) ? g_eh : g_el;
    const int kofs = (ch & 3) * 8;

    auto load_stage = [&](int s) {
        const int k0 = s * TC_CK;  // 32 halves per chunk
        const uint32_t abase = sb + TC_STAGE0 + (uint32_t)(s % TC_STAGES) * TC_STAGE_BYTES;
        const uint32_t bbase = abase + 32768u;
#pragma unroll
        for (int t = 0; t < 8; t++) {
            int idx = tid + t * 256;       // 2048 cp16 for A
            int row = idx >> 3;
            uint32_t off = (uint32_t)(row * 128 + ch * 16);
            uint32_t sw = off ^ ((off >> 3) & 0x70u);
            cp16(abase + sw, asel + (size_t)(bm + row) * KDIM + k0 + kofs);
        }
#pragma unroll
        for (int t = 0; t < 8; t++) {
            int idx = tid + t * 256;       // 2048 cp16 for B
            int row = idx >> 3;
            uint32_t off = (uint32_t)(row * 128 + ch * 16);
            uint32_t sw = off ^ ((off >> 3) & 0x70u);
            cp16(bbase + sw, bsel + (size_t)(bn + row) * KDIM + k0 + kofs);
        }
        cp_commit();
    };

    load_stage(0);
    load_stage(1);

    for (int s = 0; s < TC_CHUNKS; s++) {
        const int buf = s % TC_STAGES;
        if (s == TC_CHUNKS - 1) cp_wait0(); else cp_wait1();
        asm volatile("fence.proxy.async.shared::cta;" ::: "memory");
        __syncthreads();

        if (tid < 32) {
            if (elect_one()) {
                uint32_t abase = sb + TC_STAGE0 + (uint32_t)buf * TC_STAGE_BYTES;
                unsigned long long ad0 = make_desc(abase);
                unsigned long long ad1 = make_desc(abase + 16384u);  // rows 128..255
                unsigned long long bd = make_desc(abase + 32768u);
                // passes: (Ahi,Bhi), (Ahi,Blo), (Alo,Bhi); 2 k-steps of 16 halves each
#pragma unroll
                for (int p = 0; p < 3; p++) {
                    const int ao = (p == 2) ? 4 : 0;
                    const int bo = (p == 1) ? 4 : 0;
#pragma unroll
                    for (int ks = 0; ks < 2; ks++) {
                        uint32_t en = (s == 0 && p == 0 && ks == 0) ? 0u : 1u;
                        mma_f16_ss(tmem_base, ad0 + ao + ks * 2, bd + bo + ks * 2, en);
                        mma_f16_ss(tmem_base + 256, ad1 + ao + ks * 2, bd + bo + ks * 2, en);
                    }
                }
                TCGEN05_COMMIT(sb + TC_MBAR_OFF + buf * 8);
            }
        }

        if (s + 2 < TC_CHUNKS) {
            if (s >= 1) {
                int sp = s - 1;  // buffer (s+2)%3 was last used by stage s-1
                MBARRIER_WAIT_PARITY(sb + TC_MBAR_OFF + ((sp % TC_STAGES) * 8),
                                     (uint32_t)((sp / TC_STAGES) & 1));
            }
            load_stage(s + 2);
        }
    }
    {
        int sp = TC_CHUNKS - 1;
        MBARRIER_WAIT_PARITY(sb + TC_MBAR_OFF + ((sp % TC_STAGES) * 8),
                             (uint32_t)((sp / TC_STAGES) & 1));
    }
    TCGEN05_FENCE_AFTER();
    __syncthreads();

    // epilogue: warp w -> rows (w&3)*32 of each D tile, cols (w>>2)*128
    {
        const int w = tid >> 5;
        const int sub = w & 3;
        const int half = w >> 2;
        const int lane = tid & 31;
        const float* en = (const float*)(smem + TC_EN_OFF);
#pragma unroll
        for (int h = 0; h < 2; h++) {
            const int mrow = bm + h * 128 + sub * 32 + lane;
            unsigned long long best = ~0ull;
#pragma unroll
            for (int c0 = 0; c0 < 128; c0 += 32) {
                uint32_t r[32];
                TCGEN05_LD_32X32B_X32(r, tmem_base + h * 256 + half * 128 + c0);
                TCGEN05_WAIT_LD();
#pragma unroll
                for (int j = 0; j < 32; j++) {
                    int nl = half * 128 + c0 + j;
                    float d = en[nl] - 2.0f * __uint_as_float(r[j]);
                    unsigned long long key =
                        ((unsigned long long)fkey(d) << 32) | (unsigned)(bn + nl);
                    best = umin64(best, key);
                }
            }
            atomicMin(&g_best[mrow], best);
        }
    }
    TCGEN05_FENCE_BEFORE();
    __syncthreads();
    if (tid < 32) TCGEN05_DEALLOC(tmem_base, 512);

#else
    // ===== fallback (compile-only on the PTX pass; never runs on sm_103a) =====
    const int bm = blockIdx.y * FB_MT;
    const int bn = blockIdx.x * FB_NT;
    const uint32_t sb = smem_u32(smem);
    if (tid < FB_NT) ((float*)(smem + FB_EN))[tid] = g_enorm[bn + tid];

    const int w = tid >> 5;
    const int lane = tid & 31;
    const int g = lane >> 2;
    const int t4 = lane & 3;
    const int wm = w >> 2;
    const int wn = w & 3;

    float acc[4][4][4];
#pragma unroll
    for (int i = 0; i < 4; i++)
#pragma unroll
        for (int j = 0; j < 4; j++)
#pragma unroll
            for (int c = 0; c < 4; c++) acc[i][j][c] = 0.f;

    auto load_stage = [&](int s) {
        const int p = s >> 3;
        const int k0 = (s & 7) * 32;
        const __half* asrc = (p == 2) ? g_zl : g_zh;
        const __half* bsrc = (p == 1) ? g_el : g_eh;
        const uint32_t abase = sb + FB_STAGE0 + (uint32_t)(s & (FB_STAGES - 1)) * FB_STAGE_BYTES;
        const uint32_t bbase = abase + FB_A_TILE;
#pragma unroll
        for (int it = 0; it < 2; it++) {
            int idx = tid + it * 256;
            int row = idx >> 2, c2 = idx & 3;
            cp16(abase + (uint32_t)(row * FB_LDAB + c2 * 16),
                 asrc + (size_t)(bm + row) * KDIM + k0 + c2 * 8);
        }
#pragma unroll
        for (int it = 0; it < 2; it++) {
            int idx = tid + it * 256;
            int row = idx >> 2, c2 = idx & 3;
            cp16(bbase + (uint32_t)(row * FB_LDAB + c2 * 16),
                 bsrc + (size_t)(bn + row) * KDIM + k0 + c2 * 8);
        }
        cp_commit();
    };

    load_stage(0);
    load_stage(1);
    load_stage(2);

    for (int s = 0; s < FB_CHUNKS; s++) {
        if (s < FB_CHUNKS - 2) cp_wait2();
        else if (s == FB_CHUNKS - 2) cp_wait1();
        else cp_wait0();
        __syncthreads();
        if (s + 3 < FB_CHUNKS) load_stage(s + 3);

        const uint32_t abase = sb + FB_STAGE0 + (uint32_t)(s & (FB_STAGES - 1)) * FB_STAGE_BYTES;
        const uint32_t bbase = abase + FB_A_TILE;
        const uint32_t arow = abase + (uint32_t)((wm * 64 + g) * FB_LDAB + t4 * 4);
        const uint32_t brow = bbase + (uint32_t)((wn * 32 + g) * FB_LDAB + t4 * 4);

#pragma unroll
        for (int ks = 0; ks < 2; ks++) {
            uint32_t a[4][4];
#pragma unroll
            for (int i = 0; i < 4; i++) {
                uint32_t ab = arow + (uint32_t)(i * 16 * FB_LDAB + ks * 32);
                asm volatile("ld.shared.b32 %0, [%1];" : "=r"(a[i][0]) : "r"(ab));
                asm volatile("ld.shared.b32 %0, [%1];" : "=r"(a[i][1]) : "r"(ab + 8 * FB_LDAB));
                asm volatile("ld.shared.b32 %0, [%1];" : "=r"(a[i][2]) : "r"(ab + 16));
                asm volatile("ld.shared.b32 %0, [%1];" : "=r"(a[i][3]) : "r"(ab + 8 * FB_LDAB + 16));
            }
            uint32_t b[4][2];
#pragma unroll
            for (int j = 0; j < 4; j++) {
                uint32_t bb = brow + (uint32_t)(j * 8 * FB_LDAB + ks * 32);
                asm volatile("ld.shared.b32 %0, [%1];" : "=r"(b[j][0]) : "r"(bb));
                asm volatile("ld.shared.b32 %0, [%1];" : "=r"(b[j][1]) : "r"(bb + 16));
            }
#pragma unroll
            for (int i = 0; i < 4; i++)
#pragma unroll
                for (int j = 0; j < 4; j++) {
                    asm("mma.sync.aligned.m16n8k16.row.col.f32.f16.f16.f32 "
                        "{%0,%1,%2,%3},{%4,%5,%6,%7},{%8,%9},{%0,%1,%2,%3};"
                        : "+f"(acc[i][j][0]), "+f"(acc[i][j][1]),
                          "+f"(acc[i][j][2]), "+f"(acc[i][j][3])
                        : "r"(a[i][0]), "r"(a[i][1]), "r"(a[i][2]), "r"(a[i][3]),
                          "r"(b[j][0]), "r"(b[j][1]));
                }
        }
    }

    const float* en = (const float*)(smem + FB_EN);
#pragma unroll
    for (int i = 0; i < 4; i++) {
        const int r0 = bm + wm * 64 + i * 16 + g;
        unsigned long long k0 = ~0ull, k1 = ~0ull;
#pragma unroll
        for (int j = 0; j < 4; j++) {
            int n0 = wn * 32 + j * 8 + 2 * t4;
            float d;
            unsigned long long key;
            d = en[n0] - 2.f * acc[i][j][0];
            key = ((unsigned long long)fkey(d) << 32) | (unsigned)(bn + n0);
            k0 = umin64(k0, key);
            d = en[n0 + 1] - 2.f * acc[i][j][1];
            key = ((unsigned long long)fkey(d) << 32) | (unsigned)(bn + n0 + 1);
            k0 = umin64(k0, key);
            d = en[n0] - 2.f * acc[i][j][2];
            key = ((unsigned long long)fkey(d) << 32) | (unsigned)(bn + n0);
            k1 = umin64(k1, key);
            d = en[n0 + 1] - 2.f * acc[i][j][3];
            key = ((unsigned long long)fkey(d) << 32) | (unsigned)(bn + n0 + 1);
            k1 = umin64(k1, key);
        }
        k0 = umin64(k0, __shfl_xor_sync(0xffffffffu, k0, 1));
        k0 = umin64(k0, __shfl_xor_sync(0xffffffffu, k0, 2));
        k1 = umin64(k1, __shfl_xor_sync(0xffffffffu, k1, 1));
        k1 = umin64(k1, __shfl_xor_sync(0xffffffffu, k1, 2));
        if (t4 == 0) {
            atomicMin(&g_best[r0], k0);
            atomicMin(&g_best[r0 + 8], k1);
        }
    }
#endif
}

// ---------------- gather + loss ----------------
__global__ void gather_kernel(const float* __restrict__ z,
                              const float* __restrict__ emb,
                              float* __restrict__ out, int has_extra) {
    __shared__ float sw[8];
    const int tid = threadIdx.x;
    const int r = tid >> 6;
    const int c = tid & 63;
    const int row = blockIdx.x * 4 + r;
    unsigned long long key = g_best[row];
    int idx = (int)(key & 0xFFFFFFFFull);

    float4 q = ((const float4*)emb)[(size_t)idx * 64 + c];
    float4 zv = ((const float4*)z)[(size_t)row * 64 + c];
    ((float4*)out)[(size_t)row * 64 + c] = q;

    float dx = q.x - zv.x, dy = q.y - zv.y, dz = q.z - zv.z, dw = q.w - zv.w;
    float s = dx * dx + dy * dy + dz * dz + dw * dw;
#pragma unroll
    for (int o = 16; o; o >>= 1) s += __shfl_xor_sync(0xffffffffu, s, o);
    if ((tid & 31) == 0) sw[tid >> 5] = s;
    __syncthreads();
    if (c == 0) {
        float tot = sw[r * 2] + sw[r * 2 + 1];
        g_partial[row] = tot;
        if (has_extra) out[Q_ELEMS + 1 + row] = (float)idx;
    }
}

__global__ void finalize_kernel(float* __restrict__ out, int has_extra) {
    if (!has_extra) return;
    __shared__ float sh[256];
    int tid = threadIdx.x;
    float s = 0.f;
    for (int i = tid; i < M_ROWS; i += 256) s += g_partial[i];
    sh[tid] = s;
    __syncthreads();
#pragma unroll
    for (int o = 128; o; o >>= 1) {
        if (tid < o) sh[tid] += sh[tid + o];
        __syncthreads();
    }
    if (tid == 0) out[Q_ELEMS] = 1.25f * sh[0] / (float)Q_ELEMS;
}

// ---------------- launcher ----------------
extern "C" void kernel_launch(void* const* d_in, const int* in_sizes, int n_in,
                              void* d_out, int out_size) {
    const float* z;
    const float* emb;
    if (in_sizes[0] == M_ROWS * KDIM) {
        z = (const float*)d_in[0];
        emb = (const float*)d_in[1];
    } else {
        z = (const float*)d_in[1];
        emb = (const float*)d_in[0];
    }
    float* out = (float*)d_out;
    int has_extra = (out_size >= Q_ELEMS + 1 + M_ROWS) ? 1 : 0;

    cudaFuncSetAttribute(vq_gemm_kernel,
                         cudaFuncAttributeMaxDynamicSharedMemorySize, SMEM_LAUNCH);

    split_z_kernel<<<Q_ELEMS / 2 / 256, 256>>>(z);   // also inits g_best
    split_e_kernel<<<N_CODES * KDIM / 2 / 256, 256>>>(emb);
    enorm_kernel<<<N_CODES / 8, 256>>>(emb);

    // Grid sized for the tcgen05 body (256x256 tiles); the sm_103a cubin is
    // what the driver runs on this chip.
    dim3 grid(N_CODES / TC_NT, M_ROWS / TC_MT);  // (32, 64)
    vq_gemm_kernel<<<grid, 256, SMEM_LAUNCH>>>();

    gather_kernel<<<M_ROWS / 4, 256>>>(z, emb, out, has_extra);
    finalize_kernel<<<1, 256>>>(out, has_extra);
}

// round 9
// speedup vs baseline: 1.0915x; 1.0915x over previous
#include <cuda_runtime.h>
#include <cuda_fp16.h>
#include <stdint.h>

#define M_ROWS 16384
#define N_CODES 8192
#define KDIM 256
#define Q_ELEMS (M_ROWS * KDIM)

// ---------------- tcgen05 path config ----------------
#define TC_MT 128
#define TC_NT 128
#define TC_CK 32                 // k-halves per chunk; row = [hi 32h | lo 32h] = 128B
#define TC_STAGES 3
#define TC_CHUNKS 8              // 256 / 32 (all 3 passes per chunk)
#define TC_STAGE_BYTES 32768     // A 16KB (zh|zl) + B 16KB (eh|el)
#define TC_MBAR_OFF 64
#define TC_EN_OFF 1024
#define TC_STAGE0 2048
#define TC_TOTAL (TC_STAGE0 + TC_STAGES * TC_STAGE_BYTES)  // 100352 -> 2 CTAs/SM

// ---------------- fallback path config (compile-only on PTX pass) ----------------
#define FB_MT 128
#define FB_NT 128
#define FB_STAGES 4
#define FB_CHUNKS 24
#define FB_LDAB 80
#define FB_A_TILE (FB_MT * FB_LDAB)
#define FB_B_TILE (FB_NT * FB_LDAB)
#define FB_STAGE_BYTES (FB_A_TILE + FB_B_TILE)
#define FB_EN 0
#define FB_STAGE0 512

// The sm_103a cubin (tcgen05 body) is what the driver executes; launch smem is
// sized for it. The PTX fallback body is compile-only on this chip.
#define SMEM_LAUNCH TC_TOTAL

// ---------------- persistent scratch ----------------
__device__ unsigned long long g_best[M_ROWS];
__device__ float g_partial[M_ROWS];
__device__ float g_enorm[N_CODES];
__device__ __half g_zh[M_ROWS * KDIM];
__device__ __half g_zl[M_ROWS * KDIM];
__device__ __half g_eh[N_CODES * KDIM];
__device__ __half g_el[N_CODES * KDIM];

// ---------------- common helpers ----------------
__device__ __forceinline__ uint32_t smem_u32(const void* p) {
    uint32_t a;
    asm("{ .reg .u64 t; cvta.to.shared.u64 t, %1; cvt.u32.u64 %0, t; }"
        : "=r"(a) : "l"(p));
    return a;
}
__device__ __forceinline__ void cp16(uint32_t dst, const void* src) {
    asm volatile("cp.async.cg.shared.global [%0], [%1], 16;" :: "r"(dst), "l"(src));
}
__device__ __forceinline__ void cp_commit() { asm volatile("cp.async.commit_group;"); }
__device__ __forceinline__ void cp_wait2() { asm volatile("cp.async.wait_group 2;" ::: "memory"); }
__device__ __forceinline__ void cp_wait1() { asm volatile("cp.async.wait_group 1;" ::: "memory"); }
__device__ __forceinline__ void cp_wait0() { asm volatile("cp.async.wait_group 0;" ::: "memory"); }

__device__ __forceinline__ unsigned fkey(float f) {
    unsigned u = __float_as_uint(f);
    return (u & 0x80000000u) ? ~u : (u | 0x80000000u);
}
__device__ __forceinline__ unsigned long long umin64(unsigned long long a,
                                                     unsigned long long b) {
    return a < b ? a : b;
}

// ---------------- tcgen05 helpers (sm_103a cubin pass only) ----------------
#if defined(__CUDA_ARCH_FEAT_SM103_ALL)

__device__ __forceinline__ uint32_t elect_one() {
    uint32_t pred;
    asm volatile(
        "{\n\t.reg .pred p;\n\telect.sync _|p, 0xFFFFFFFF;\n\t"
        "selp.b32 %0, 1, 0, p;\n\t}" : "=r"(pred));
    return pred;
}

#define MBARRIER_INIT(addr, cnt) \
    asm volatile("mbarrier.init.shared.b64 [%0], %1;" :: "r"(addr), "r"(cnt) : "memory")

#define MBARRIER_WAIT_PARITY(mbar, parity) do {                                   \
    uint32_t _m = (mbar); uint32_t _p = (parity); uint32_t _done;                 \
    asm volatile("{\n\t.reg .pred p;\n\t"                                         \
        "mbarrier.try_wait.parity.acquire.cta.shared::cta.b64 p, [%1], %2;\n\t"   \
        "selp.b32 %0, 1, 0, p;\n\t}" : "=r"(_done) : "r"(_m), "r"(_p) : "memory");\
    if (!_done) {                                                                 \
        asm volatile("{\n\t.reg .pred P1;\n\t"                                    \
            "WAIT_LOOP_%=:\n\t"                                                   \
            "mbarrier.try_wait.parity.acquire.cta.shared::cta.b64 P1, [%0], %1, 0x989680;\n\t" \
            "@P1 bra.uni WAIT_DONE_%=;\n\t"                                       \
            "bra.uni WAIT_LOOP_%=;\n\t"                                           \
            "WAIT_DONE_%=:\n\t}" :: "r"(_m), "r"(_p) : "memory");                 \
    }                                                                             \
} while (0)

#define TCGEN05_ALLOC(smem_dst, ncols) \
    asm volatile("tcgen05.alloc.cta_group::1.sync.aligned.shared::cta.b32 [%0], %1;" \
                 :: "r"(smem_dst), "r"(ncols) : "memory")
#define TCGEN05_DEALLOC(tmem, ncols) \
    asm volatile("tcgen05.dealloc.cta_group::1.sync.aligned.b32 %0, %1;" :: "r"(tmem), "r"(ncols))
#define TCGEN05_RELINQUISH() \
    asm volatile("tcgen05.relinquish_alloc_permit.cta_group::1.sync.aligned;")
#define TCGEN05_COMMIT(mbar) \
    asm volatile("tcgen05.commit.cta_group::1.mbarrier::arrive::one.shared::cluster.b64 [%0];" \
                 :: "r"(mbar) : "memory")
#define TCGEN05_FENCE_AFTER() asm volatile("tcgen05.fence::after_thread_sync;" ::: "memory")
#define TCGEN05_FENCE_BEFORE() asm volatile("tcgen05.fence::before_thread_sync;" ::: "memory")
#define TCGEN05_WAIT_LD() asm volatile("tcgen05.wait::ld.sync.aligned;" ::: "memory")

#define TCGEN05_LD_32X32B_X32(r, tmem_addr) \
    asm volatile( \
        "tcgen05.ld.sync.aligned.32x32b.x32.b32 " \
        "{%0, %1, %2, %3, %4, %5, %6, %7, " \
        " %8, %9, %10, %11, %12, %13, %14, %15, " \
        " %16, %17, %18, %19, %20, %21, %22, %23, " \
        " %24, %25, %26, %27, %28, %29, %30, %31}, [%32];" \
        : "=r"((r)[0]),  "=r"((r)[1]),  "=r"((r)[2]),  "=r"((r)[3]), \
          "=r"((r)[4]),  "=r"((r)[5]),  "=r"((r)[6]),  "=r"((r)[7]), \
          "=r"((r)[8]),  "=r"((r)[9]),  "=r"((r)[10]), "=r"((r)[11]), \
          "=r"((r)[12]), "=r"((r)[13]), "=r"((r)[14]), "=r"((r)[15]), \
          "=r"((r)[16]), "=r"((r)[17]), "=r"((r)[18]), "=r"((r)[19]), \
          "=r"((r)[20]), "=r"((r)[21]), "=r"((r)[22]), "=r"((r)[23]), \
          "=r"((r)[24]), "=r"((r)[25]), "=r"((r)[26]), "=r"((r)[27]), \
          "=r"((r)[28]), "=r"((r)[29]), "=r"((r)[30]), "=r"((r)[31]) \
        : "r"(tmem_addr))

// SW128 descriptor: version=1, LBO=1, SBO=64 (128B rows, 8x128B atom)
static __device__ __forceinline__ unsigned long long make_desc(uint32_t addr) {
    const unsigned long long base =
        (2ull << 61) | (1ull << 46) | (64ull << 32) | (1ull << 16);
    return base | ((unsigned long long)(addr >> 4) & 0x3FFFull);
}

// idesc: D=F32(1@4), A=FP16(0@7), B=FP16(0@10), N/8@17, M/16@24 (M=128 per MMA)
#define TC_IDESC ((1u << 4) | ((TC_NT / 8) << 17) | (8u << 24))

__device__ __forceinline__ void mma_f16_ss(uint32_t d, unsigned long long ad,
                                           unsigned long long bd, uint32_t en) {
    asm volatile(
        "{\n\t.reg .pred p;\n\t"
        "setp.ne.u32 p, %5, 0;\n\t"
        "tcgen05.mma.cta_group::1.kind::f16 [%0], %1, %2, %3, {%4, %4, %4, %4}, p;\n\t}"
        :: "r"(d), "l"(ad), "l"(bd), "r"((uint32_t)TC_IDESC), "r"(0u), "r"(en)
        : "memory");
}

#endif  // __CUDA_ARCH_FEAT_SM103_ALL

// ---------------- prep kernels ----------------
__global__ void split_z_kernel(const float* __restrict__ src) {
    int gid = blockIdx.x * 256 + threadIdx.x;
    float2 v = ((const float2*)src)[gid];
    __half h0 = __float2half(v.x);
    __half l0 = __float2half(v.x - __half2float(h0));
    __half h1 = __float2half(v.y);
    __half l1 = __float2half(v.y - __half2float(h1));
    *(__half2*)(g_zh + 2 * gid) = __halves2half2(h0, h1);
    *(__half2*)(g_zl + 2 * gid) = __halves2half2(l0, l1);
    if (gid < M_ROWS) g_best[gid] = ~0ull;
}

__global__ void split_e_kernel(const float* __restrict__ src) {
    int gid = blockIdx.x * 256 + threadIdx.x;
    float2 v = ((const float2*)src)[gid];
    __half h0 = __float2half(v.x);
    __half l0 = __float2half(v.x - __half2float(h0));
    __half h1 = __float2half(v.y);
    __half l1 = __float2half(v.y - __half2float(h1));
    *(__half2*)(g_eh + 2 * gid) = __halves2half2(h0, h1);
    *(__half2*)(g_el + 2 * gid) = __halves2half2(l0, l1);
}

__global__ void enorm_kernel(const float* __restrict__ emb) {
    int row = blockIdx.x * (blockDim.x >> 5) + (threadIdx.x >> 5);
    int lane = threadIdx.x & 31;
    if (row >= N_CODES) return;
    const float* e = emb + (size_t)row * KDIM;
    float s = 0.f;
#pragma unroll
    for (int c = lane; c < KDIM; c += 32) {
        float v = e[c];
        s = fmaf(v, v, s);
    }
#pragma unroll
    for (int o = 16; o; o >>= 1) s += __shfl_xor_sync(0xffffffffu, s, o);
    if (lane == 0) g_enorm[row] = s;
}

// ---------------- GEMM + argmin (dual body; cubin pass runs tcgen05) ----------------
__global__ void __launch_bounds__(256, 2) vq_gemm_kernel() {
    extern __shared__ __align__(1024) char smem[];
    const int tid = threadIdx.x;

#if defined(__CUDA_ARCH_FEAT_SM103_ALL)
    // ===== tcgen05 fp16 path: 128x128 tile, 2 CTAs/SM; k-outer [hi|lo] rows =====
    const int bm = blockIdx.y * TC_MT;
    const int bn = blockIdx.x * TC_NT;
    const uint32_t sb = smem_u32(smem);

    if (tid < 32) {
        TCGEN05_ALLOC(sb, 128);
        TCGEN05_RELINQUISH();
    }
    if (tid == 0) {
        MBARRIER_INIT(sb + TC_MBAR_OFF + 0, 1);
        MBARRIER_INIT(sb + TC_MBAR_OFF + 8, 1);
        MBARRIER_INIT(sb + TC_MBAR_OFF + 16, 1);
    }
    if (tid < TC_NT) ((float*)(smem + TC_EN_OFF))[tid] = g_enorm[bn + tid];
    __syncthreads();

    uint32_t tmem_base;
    asm volatile("ld.shared.b32 %0, [%1];" : "=r"(tmem_base) : "r"(sb));

    // fixed 16B-column per thread: ch 0..7; ch<4 -> hi source, ch>=4 -> lo source
    const int ch = tid & 7;
    const __half* asel = (ch < 4) ? g_zh : g_zl;
    const __half* bsel = (ch < 4) ? g_eh : g_el;
    const int kofs = (ch & 3) * 8;

    auto load_stage = [&](int s) {
        const int k0 = s * TC_CK;
        const uint32_t abase = sb + TC_STAGE0 + (uint32_t)(s % TC_STAGES) * TC_STAGE_BYTES;
        const uint32_t bbase = abase + 16384u;
#pragma unroll
        for (int t = 0; t < 4; t++) {
            int idx = tid + t * 256;       // 1024 cp16 for A (128 rows x 8 cols)
            int row = idx >> 3;
            uint32_t off = (uint32_t)(row * 128 + ch * 16);
            uint32_t sw = off ^ ((off >> 3) & 0x70u);
            cp16(abase + sw, asel + (size_t)(bm + row) * KDIM + k0 + kofs);
        }
#pragma unroll
        for (int t = 0; t < 4; t++) {
            int idx = tid + t * 256;       // 1024 cp16 for B
            int row = idx >> 3;
            uint32_t off = (uint32_t)(row * 128 + ch * 16);
            uint32_t sw = off ^ ((off >> 3) & 0x70u);
            cp16(bbase + sw, bsel + (size_t)(bn + row) * KDIM + k0 + kofs);
        }
        cp_commit();
    };

    load_stage(0);
    load_stage(1);

    for (int s = 0; s < TC_CHUNKS; s++) {
        const int buf = s % TC_STAGES;
        if (s == TC_CHUNKS - 1) cp_wait0(); else cp_wait1();
        asm volatile("fence.proxy.async.shared::cta;" ::: "memory");
        __syncthreads();

        if (tid < 32) {
            if (elect_one()) {
                uint32_t abase = sb + TC_STAGE0 + (uint32_t)buf * TC_STAGE_BYTES;
                unsigned long long ad = make_desc(abase);
                unsigned long long bd = make_desc(abase + 16384u);
                // passes: (Ahi,Bhi), (Ahi,Blo), (Alo,Bhi); 2 k-steps of 16 halves
#pragma unroll
                for (int p = 0; p < 3; p++) {
                    const int ao = (p == 2) ? 4 : 0;
                    const int bo = (p == 1) ? 4 : 0;
#pragma unroll
                    for (int ks = 0; ks < 2; ks++) {
                        uint32_t en = (s == 0 && p == 0 && ks == 0) ? 0u : 1u;
                        mma_f16_ss(tmem_base, ad + ao + ks * 2, bd + bo + ks * 2, en);
                    }
                }
                TCGEN05_COMMIT(sb + TC_MBAR_OFF + buf * 8);
            }
        }

        if (s + 2 < TC_CHUNKS) {
            if (s >= 1) {
                int sp = s - 1;  // buffer (s+2)%3 last used by chunk s-1
                MBARRIER_WAIT_PARITY(sb + TC_MBAR_OFF + ((sp % TC_STAGES) * 8),
                                     (uint32_t)((sp / TC_STAGES) & 1));
            }
            load_stage(s + 2);
        }
    }
    {
        int sp = TC_CHUNKS - 1;
        MBARRIER_WAIT_PARITY(sb + TC_MBAR_OFF + ((sp % TC_STAGES) * 8),
                             (uint32_t)((sp / TC_STAGES) & 1));
    }
    TCGEN05_FENCE_AFTER();
    __syncthreads();

    // epilogue: warp w -> rows (w&3)*32, cols (w>>2)*64; cheap compare-select,
    // one fkey+pack per row at the end (ascending cols + strict '<' keeps the
    // lowest index on ties, matching argmin).
    {
        const int w = tid >> 5;
        const int sub = w & 3;
        const int half = w >> 2;
        const int lane = tid & 31;
        const float* en = (const float*)(smem + TC_EN_OFF);
        const int mrow = bm + sub * 32 + lane;
        float dmin = 3.4e38f;
        int besti = 0;
#pragma unroll
        for (int c0 = 0; c0 < 64; c0 += 32) {
            uint32_t r[32];
            TCGEN05_LD_32X32B_X32(r, tmem_base + half * 64 + c0);
            TCGEN05_WAIT_LD();
#pragma unroll
            for (int j = 0; j < 32; j++) {
                int nl = half * 64 + c0 + j;
                float d = en[nl] - 2.0f * __uint_as_float(r[j]);
                if (d < dmin) { dmin = d; besti = nl; }
            }
        }
        unsigned long long key =
            ((unsigned long long)fkey(dmin) << 32) | (unsigned)(bn + besti);
        atomicMin(&g_best[mrow], key);
    }
    TCGEN05_FENCE_BEFORE();
    __syncthreads();
    if (tid < 32) TCGEN05_DEALLOC(tmem_base, 128);

#else
    // ===== fallback (compile-only on the PTX pass; never runs on sm_103a) =====
    const int bm = blockIdx.y * FB_MT;
    const int bn = blockIdx.x * FB_NT;
    const uint32_t sb = smem_u32(smem);
    if (tid < FB_NT) ((float*)(smem + FB_EN))[tid] = g_enorm[bn + tid];

    const int w = tid >> 5;
    const int lane = tid & 31;
    const int g = lane >> 2;
    const int t4 = lane & 3;
    const int wm = w >> 2;
    const int wn = w & 3;

    float acc[4][4][4];
#pragma unroll
    for (int i = 0; i < 4; i++)
#pragma unroll
        for (int j = 0; j < 4; j++)
#pragma unroll
            for (int c = 0; c < 4; c++) acc[i][j][c] = 0.f;

    auto load_stage = [&](int s) {
        const int p = s >> 3;
        const int k0 = (s & 7) * 32;
        const __half* asrc = (p == 2) ? g_zl : g_zh;
        const __half* bsrc = (p == 1) ? g_el : g_eh;
        const uint32_t abase = sb + FB_STAGE0 + (uint32_t)(s & (FB_STAGES - 1)) * FB_STAGE_BYTES;
        const uint32_t bbase = abase + FB_A_TILE;
#pragma unroll
        for (int it = 0; it < 2; it++) {
            int idx = tid + it * 256;
            int row = idx >> 2, c2 = idx & 3;
            cp16(abase + (uint32_t)(row * FB_LDAB + c2 * 16),
                 asrc + (size_t)(bm + row) * KDIM + k0 + c2 * 8);
        }
#pragma unroll
        for (int it = 0; it < 2; it++) {
            int idx = tid + it * 256;
            int row = idx >> 2, c2 = idx & 3;
            cp16(bbase + (uint32_t)(row * FB_LDAB + c2 * 16),
                 bsrc + (size_t)(bn + row) * KDIM + k0 + c2 * 8);
        }
        cp_commit();
    };

    load_stage(0);
    load_stage(1);
    load_stage(2);

    for (int s = 0; s < FB_CHUNKS; s++) {
        if (s < FB_CHUNKS - 2) cp_wait2();
        else if (s == FB_CHUNKS - 2) cp_wait1();
        else cp_wait0();
        __syncthreads();
        if (s + 3 < FB_CHUNKS) load_stage(s + 3);

        const uint32_t abase = sb + FB_STAGE0 + (uint32_t)(s & (FB_STAGES - 1)) * FB_STAGE_BYTES;
        const uint32_t bbase = abase + FB_A_TILE;
        const uint32_t arow = abase + (uint32_t)((wm * 64 + g) * FB_LDAB + t4 * 4);
        const uint32_t brow = bbase + (uint32_t)((wn * 32 + g) * FB_LDAB + t4 * 4);

#pragma unroll
        for (int ks = 0; ks < 2; ks++) {
            uint32_t a[4][4];
#pragma unroll
            for (int i = 0; i < 4; i++) {
                uint32_t ab = arow + (uint32_t)(i * 16 * FB_LDAB + ks * 32);
                asm volatile("ld.shared.b32 %0, [%1];" : "=r"(a[i][0]) : "r"(ab));
                asm volatile("ld.shared.b32 %0, [%1];" : "=r"(a[i][1]) : "r"(ab + 8 * FB_LDAB));
                asm volatile("ld.shared.b32 %0, [%1];" : "=r"(a[i][2]) : "r"(ab + 16));
                asm volatile("ld.shared.b32 %0, [%1];" : "=r"(a[i][3]) : "r"(ab + 8 * FB_LDAB + 16));
            }
            uint32_t b[4][2];
#pragma unroll
            for (int j = 0; j < 4; j++) {
                uint32_t bb = brow + (uint32_t)(j * 8 * FB_LDAB + ks * 32);
                asm volatile("ld.shared.b32 %0, [%1];" : "=r"(b[j][0]) : "r"(bb));
                asm volatile("ld.shared.b32 %0, [%1];" : "=r"(b[j][1]) : "r"(bb + 16));
            }
#pragma unroll
            for (int i = 0; i < 4; i++)
#pragma unroll
                for (int j = 0; j < 4; j++) {
                    asm("mma.sync.aligned.m16n8k16.row.col.f32.f16.f16.f32 "
                        "{%0,%1,%2,%3},{%4,%5,%6,%7},{%8,%9},{%0,%1,%2,%3};"
                        : "+f"(acc[i][j][0]), "+f"(acc[i][j][1]),
                          "+f"(acc[i][j][2]), "+f"(acc[i][j][3])
                        : "r"(a[i][0]), "r"(a[i][1]), "r"(a[i][2]), "r"(a[i][3]),
                          "r"(b[j][0]), "r"(b[j][1]));
                }
        }
    }

    const float* en = (const float*)(smem + FB_EN);
#pragma unroll
    for (int i = 0; i < 4; i++) {
        const int r0 = bm + wm * 64 + i * 16 + g;
        unsigned long long k0 = ~0ull, k1 = ~0ull;
#pragma unroll
        for (int j = 0; j < 4; j++) {
            int n0 = wn * 32 + j * 8 + 2 * t4;
            float d;
            unsigned long long key;
            d = en[n0] - 2.f * acc[i][j][0];
            key = ((unsigned long long)fkey(d) << 32) | (unsigned)(bn + n0);
            k0 = umin64(k0, key);
            d = en[n0 + 1] - 2.f * acc[i][j][1];
            key = ((unsigned long long)fkey(d) << 32) | (unsigned)(bn + n0 + 1);
            k0 = umin64(k0, key);
            d = en[n0] - 2.f * acc[i][j][2];
            key = ((unsigned long long)fkey(d) << 32) | (unsigned)(bn + n0);
            k1 = umin64(k1, key);
            d = en[n0 + 1] - 2.f * acc[i][j][3];
            key = ((unsigned long long)fkey(d) << 32) | (unsigned)(bn + n0 + 1);
            k1 = umin64(k1, key);
        }
        k0 = umin64(k0, __shfl_xor_sync(0xffffffffu, k0, 1));
        k0 = umin64(k0, __shfl_xor_sync(0xffffffffu, k0, 2));
        k1 = umin64(k1, __shfl_xor_sync(0xffffffffu, k1, 1));
        k1 = umin64(k1, __shfl_xor_sync(0xffffffffu, k1, 2));
        if (t4 == 0) {
            atomicMin(&g_best[r0], k0);
            atomicMin(&g_best[r0 + 8], k1);
        }
    }
#endif
}

// ---------------- gather + loss ----------------
__global__ void gather_kernel(const float* __restrict__ z,
                              const float* __restrict__ emb,
                              float* __restrict__ out, int has_extra) {
    __shared__ float sw[8];
    const int tid = threadIdx.x;
    const int r = tid >> 6;
    const int c = tid & 63;
    const int row = blockIdx.x * 4 + r;
    unsigned long long key = g_best[row];
    int idx = (int)(key & 0xFFFFFFFFull);

    float4 q = ((const float4*)emb)[(size_t)idx * 64 + c];
    float4 zv = ((const float4*)z)[(size_t)row * 64 + c];
    ((float4*)out)[(size_t)row * 64 + c] = q;

    float dx = q.x - zv.x, dy = q.y - zv.y, dz = q.z - zv.z, dw = q.w - zv.w;
    float s = dx * dx + dy * dy + dz * dz + dw * dw;
#pragma unroll
    for (int o = 16; o; o >>= 1) s += __shfl_xor_sync(0xffffffffu, s, o);
    if ((tid & 31) == 0) sw[tid >> 5] = s;
    __syncthreads();
    if (c == 0) {
        float tot = sw[r * 2] + sw[r * 2 + 1];
        g_partial[row] = tot;
        if (has_extra) out[Q_ELEMS + 1 + row] = (float)idx;
    }
}

__global__ void finalize_kernel(float* __restrict__ out, int has_extra) {
    if (!has_extra) return;
    __shared__ float sh[256];
    int tid = threadIdx.x;
    float s = 0.f;
    for (int i = tid; i < M_ROWS; i += 256) s += g_partial[i];
    sh[tid] = s;
    __syncthreads();
#pragma unroll
    for (int o = 128; o; o >>= 1) {
        if (tid < o) sh[tid] += sh[tid + o];
        __syncthreads();
    }
    if (tid == 0) out[Q_ELEMS] = 1.25f * sh[0] / (float)Q_ELEMS;
}

// ---------------- launcher ----------------
extern "C" void kernel_launch(void* const* d_in, const int* in_sizes, int n_in,
                              void* d_out, int out_size) {
    const float* z;
    const float* emb;
    if (in_sizes[0] == M_ROWS * KDIM) {
        z = (const float*)d_in[0];
        emb = (const float*)d_in[1];
    } else {
        z = (const float*)d_in[1];
        emb = (const float*)d_in[0];
    }
    float* out = (float*)d_out;
    int has_extra = (out_size >= Q_ELEMS + 1 + M_ROWS) ? 1 : 0;

    cudaFuncSetAttribute(vq_gemm_kernel,
                         cudaFuncAttributeMaxDynamicSharedMemorySize, SMEM_LAUNCH);

    split_z_kernel<<<Q_ELEMS / 2 / 256, 256>>>(z);   // also inits g_best
    split_e_kernel<<<N_CODES * KDIM / 2 / 256, 256>>>(emb);
    enorm_kernel<<<N_CODES / 8, 256>>>(emb);

    dim3 grid(N_CODES / TC_NT, M_ROWS / TC_MT);  // (64, 128) = 8192 CTAs, 2/SM
    vq_gemm_kernel<<<grid, 256, SMEM_LAUNCH>>>();

    gather_kernel<<<M_ROWS / 4, 256>>>(z, emb, out, has_extra);
    finalize_kernel<<<1, 256>>>(out, has_extra);
}

// round 10
// speedup vs baseline: 1.4159x; 1.2973x over previous
#include <cuda_runtime.h>
#include <cuda_fp16.h>
#include <stdint.h>

#define M_ROWS 16384
#define N_CODES 8192
#define KDIM 256
#define Q_ELEMS (M_ROWS * KDIM)

#define TC_MT 256
#define TC_NT 256
#define N_TILES 2048            // (16384/256) * (8192/256) = 64*32
#define GEMM_GRID 148
#define TC_STAGES 3
#define TC_STAGE_BYTES 65536    // A 32KB + B 32KB per chunk
#define TC_MBAR_OFF 64          // 6 mbars: load0/1/2 @64/72/80, mma0/1/2 @88/96/104
#define TC_EN_OFF 1024
#define TC_STAGE0 2048
#define TC_TOTAL (TC_STAGE0 + TC_STAGES * TC_STAGE_BYTES)  // 198656

// fallback config (compile-only on the plain-PTX pass)
#define FB_MT 128
#define FB_NT 128
#define FB_STAGES 4
#define FB_CHUNKS 24
#define FB_LDAB 80
#define FB_A_TILE (FB_MT * FB_LDAB)
#define FB_B_TILE (FB_NT * FB_LDAB)
#define FB_STAGE_BYTES (FB_A_TILE + FB_B_TILE)
#define FB_EN 0
#define FB_STAGE0 512

// ---------------- persistent scratch ----------------
__device__ unsigned long long g_best[M_ROWS];
__device__ float g_partial[M_ROWS];
__device__ float g_enorm[N_CODES];
// packed, pre-swizzled operand blocks: [(tile*8+chunk)] -> 32KB contiguous
__device__ __align__(1024) uint4 g_za[(M_ROWS / 256) * 8 * 256 * 8];   // 16 MB
__device__ __align__(1024) uint4 g_zb[(N_CODES / 256) * 8 * 256 * 8];  // 8 MB
// split halves for the fallback body only (it never runs on sm_103a)
__device__ __half g_zh[1];
__device__ __half g_zl[1];
__device__ __half g_eh[1];
__device__ __half g_el[1];

// ---------------- common helpers ----------------
__device__ __forceinline__ uint32_t smem_u32(const void* p) {
    uint32_t a;
    asm("{ .reg .u64 t; cvta.to.shared.u64 t, %1; cvt.u32.u64 %0, t; }"
        : "=r"(a) : "l"(p));
    return a;
}
__device__ __forceinline__ unsigned fkey(float f) {
    unsigned u = __float_as_uint(f);
    return (u & 0x80000000u) ? ~u : (u | 0x80000000u);
}
__device__ __forceinline__ unsigned long long umin64(unsigned long long a,
                                                     unsigned long long b) {
    return a < b ? a : b;
}
__device__ __forceinline__ uint32_t h2u(__half a, __half b) {
    __half2 p = __halves2half2(a, b);
    return *reinterpret_cast<uint32_t*>(&p);
}

// ---------------- tcgen05 / TMA helpers (sm_103a cubin pass only) ----------------
#if defined(__CUDA_ARCH_FEAT_SM103_ALL)

#define MBARRIER_INIT(addr, cnt) \
    asm volatile("mbarrier.init.shared.b64 [%0], %1;" :: "r"(addr), "r"(cnt) : "memory")

#define MBARRIER_EXPECT_TX(mbar, bytes) \
    asm volatile("mbarrier.arrive.expect_tx.shared.b64 _, [%0], %1;" \
                 :: "r"(mbar), "r"(bytes) : "memory")

#define CP_BULK(dst, src, bytes, mbar) \
    asm volatile("cp.async.bulk.shared::cluster.global.mbarrier::complete_tx::bytes " \
                 "[%0], [%1], %2, [%3];" \
                 :: "r"(dst), "l"(src), "r"(bytes), "r"(mbar) : "memory")

#define MBARRIER_WAIT_PARITY(mbar, parity) do {                                   \
    uint32_t _m = (mbar); uint32_t _p = (parity); uint32_t _done;                 \
    asm volatile("{\n\t.reg .pred p;\n\t"                                         \
        "mbarrier.try_wait.parity.acquire.cta.shared::cta.b64 p, [%1], %2;\n\t"   \
        "selp.b32 %0, 1, 0, p;\n\t}" : "=r"(_done) : "r"(_m), "r"(_p) : "memory");\
    if (!_done) {                                                                 \
        asm volatile("{\n\t.reg .pred P1;\n\t"                                    \
            "WAIT_LOOP_%=:\n\t"                                                   \
            "mbarrier.try_wait.parity.acquire.cta.shared::cta.b64 P1, [%0], %1, 0x989680;\n\t" \
            "@P1 bra.uni WAIT_DONE_%=;\n\t"                                       \
            "bra.uni WAIT_LOOP_%=;\n\t"                                           \
            "WAIT_DONE_%=:\n\t}" :: "r"(_m), "r"(_p) : "memory");                 \
    }                                                                             \
} while (0)

#define TCGEN05_ALLOC(smem_dst, ncols) \
    asm volatile("tcgen05.alloc.cta_group::1.sync.aligned.shared::cta.b32 [%0], %1;" \
                 :: "r"(smem_dst), "r"(ncols) : "memory")
#define TCGEN05_DEALLOC(tmem, ncols) \
    asm volatile("tcgen05.dealloc.cta_group::1.sync.aligned.b32 %0, %1;" :: "r"(tmem), "r"(ncols))
#define TCGEN05_RELINQUISH() \
    asm volatile("tcgen05.relinquish_alloc_permit.cta_group::1.sync.aligned;")
#define TCGEN05_COMMIT(mbar) \
    asm volatile("tcgen05.commit.cta_group::1.mbarrier::arrive::one.shared::cluster.b64 [%0];" \
                 :: "r"(mbar) : "memory")
#define TCGEN05_FENCE_AFTER() asm volatile("tcgen05.fence::after_thread_sync;" ::: "memory")
#define TCGEN05_FENCE_BEFORE() asm volatile("tcgen05.fence::before_thread_sync;" ::: "memory")
#define TCGEN05_WAIT_LD() asm volatile("tcgen05.wait::ld.sync.aligned;" ::: "memory")

#define TCGEN05_LD_32X32B_X32(r, tmem_addr) \
    asm volatile( \
        "tcgen05.ld.sync.aligned.32x32b.x32.b32 " \
        "{%0, %1, %2, %3, %4, %5, %6, %7, " \
        " %8, %9, %10, %11, %12, %13, %14, %15, " \
        " %16, %17, %18, %19, %20, %21, %22, %23, " \
        " %24, %25, %26, %27, %28, %29, %30, %31}, [%32];" \
        : "=r"((r)[0]),  "=r"((r)[1]),  "=r"((r)[2]),  "=r"((r)[3]), \
          "=r"((r)[4]),  "=r"((r)[5]),  "=r"((r)[6]),  "=r"((r)[7]), \
          "=r"((r)[8]),  "=r"((r)[9]),  "=r"((r)[10]), "=r"((r)[11]), \
          "=r"((r)[12]), "=r"((r)[13]), "=r"((r)[14]), "=r"((r)[15]), \
          "=r"((r)[16]), "=r"((r)[17]), "=r"((r)[18]), "=r"((r)[19]), \
          "=r"((r)[20]), "=r"((r)[21]), "=r"((r)[22]), "=r"((r)[23]), \
          "=r"((r)[24]), "=r"((r)[25]), "=r"((r)[26]), "=r"((r)[27]), \
          "=r"((r)[28]), "=r"((r)[29]), "=r"((r)[30]), "=r"((r)[31]) \
        : "r"(tmem_addr))

// SW128 descriptor: version=1, LBO=1, SBO=64 (128B rows, 8x128B atom)
static __device__ __forceinline__ unsigned long long make_desc(uint32_t addr) {
    const unsigned long long base =
        (2ull << 61) | (1ull << 46) | (64ull << 32) | (1ull << 16);
    return base | ((unsigned long long)(addr >> 4) & 0x3FFFull);
}

// idesc: D=F32(1@4), A=FP16, B=FP16, N=256 (32@17), M=128 (8@24)
#define TC_IDESC ((1u << 4) | ((TC_NT / 8) << 17) | (8u << 24))

__device__ __forceinline__ void mma_f16_ss(uint32_t d, unsigned long long ad,
                                           unsigned long long bd, uint32_t en) {
    asm volatile(
        "{\n\t.reg .pred p;\n\t"
        "setp.ne.u32 p, %5, 0;\n\t"
        "tcgen05.mma.cta_group::1.kind::f16 [%0], %1, %2, %3, {%4, %4, %4, %4}, p;\n\t}"
        :: "r"(d), "l"(ad), "l"(bd), "r"((uint32_t)TC_IDESC), "r"(0u), "r"(en)
        : "memory");
}

#endif  // __CUDA_ARCH_FEAT_SM103_ALL

// fallback cp.async helpers (used only by the never-executed PTX-pass body)
__device__ __forceinline__ void cp16(uint32_t dst, const void* src) {
    asm volatile("cp.async.cg.shared.global [%0], [%1], 16;" :: "r"(dst), "l"(src));
}
__device__ __forceinline__ void cp_commit() { asm volatile("cp.async.commit_group;"); }
__device__ __forceinline__ void cp_wait2() { asm volatile("cp.async.wait_group 2;" ::: "memory"); }
__device__ __forceinline__ void cp_wait1() { asm volatile("cp.async.wait_group 1;" ::: "memory"); }
__device__ __forceinline__ void cp_wait0() { asm volatile("cp.async.wait_group 0;" ::: "memory"); }

// ---------------- prep kernels: split + pack + pre-swizzle ----------------
// layout: block (tile256, chunk s) = 256 rows x 128B, row r unit u (16B):
//   u = c ^ (r&7) holds hi halves k0+c*8..+8; u = (c+4)^(r&7) holds lo halves.
__global__ void pack_z_kernel(const float* __restrict__ src) {
    int gid = blockIdx.x * 256 + threadIdx.x;   // 524288: c(2b) s(3b) grow(14b)
    int c = gid & 3, s = (gid >> 2) & 7, grow = gid >> 5;
    const float4* z4 = (const float4*)(src + (size_t)grow * KDIM + s * 32 + c * 8);
    float4 a = z4[0], b = z4[1];
    __half h0 = __float2half(a.x), h1 = __float2half(a.y);
    __half h2 = __float2half(a.z), h3 = __float2half(a.w);
    __half h4 = __float2half(b.x), h5 = __float2half(b.y);
    __half h6 = __float2half(b.z), h7 = __float2half(b.w);
    uint4 hv, lv;
    hv.x = h2u(h0, h1); hv.y = h2u(h2, h3); hv.z = h2u(h4, h5); hv.w = h2u(h6, h7);
    lv.x = h2u(__float2half(a.x - __half2float(h0)), __float2half(a.y - __half2float(h1)));
    lv.y = h2u(__float2half(a.z - __half2float(h2)), __float2half(a.w - __half2float(h3)));
    lv.z = h2u(__float2half(b.x - __half2float(h4)), __float2half(b.y - __half2float(h5)));
    lv.w = h2u(__float2half(b.z - __half2float(h6)), __float2half(b.w - __half2float(h7)));
    int mt = grow >> 8, r = grow & 255;
    size_t rowbase = ((size_t)(mt * 8 + s) * 256 + r) * 8;
    g_za[rowbase + (c ^ (r & 7))] = hv;
    g_za[rowbase + ((c + 4) ^ (r & 7))] = lv;
    if (gid < M_ROWS) g_best[gid] = ~0ull;
}

__global__ void pack_e_kernel(const float* __restrict__ src) {
    int gid = blockIdx.x * 256 + threadIdx.x;   // 262144
    int c = gid & 3, s = (gid >> 2) & 7, grow = gid >> 5;
    const float4* e4 = (const float4*)(src + (size_t)grow * KDIM + s * 32 + c * 8);
    float4 a = e4[0], b = e4[1];
    __half h0 = __float2half(a.x), h1 = __float2half(a.y);
    __half h2 = __float2half(a.z), h3 = __float2half(a.w);
    __half h4 = __float2half(b.x), h5 = __float2half(b.y);
    __half h6 = __float2half(b.z), h7 = __float2half(b.w);
    uint4 hv, lv;
    hv.x = h2u(h0, h1); hv.y = h2u(h2, h3); hv.z = h2u(h4, h5); hv.w = h2u(h6, h7);
    lv.x = h2u(__float2half(a.x - __half2float(h0)), __float2half(a.y - __half2float(h1)));
    lv.y = h2u(__float2half(a.z - __half2float(h2)), __float2half(a.w - __half2float(h3)));
    lv.z = h2u(__float2half(b.x - __half2float(h4)), __float2half(b.y - __half2float(h5)));
    lv.w = h2u(__float2half(b.z - __half2float(h6)), __float2half(b.w - __half2float(h7)));
    int nt = grow >> 8, r = grow & 255;
    size_t rowbase = ((size_t)(nt * 8 + s) * 256 + r) * 8;
    g_zb[rowbase + (c ^ (r & 7))] = hv;
    g_zb[rowbase + ((c + 4) ^ (r & 7))] = lv;
}

__global__ void enorm_kernel(const float* __restrict__ emb) {
    int row = blockIdx.x * (blockDim.x >> 5) + (threadIdx.x >> 5);
    int lane = threadIdx.x & 31;
    if (row >= N_CODES) return;
    const float* e = emb + (size_t)row * KDIM;
    float s = 0.f;
#pragma unroll
    for (int c = lane; c < KDIM; c += 32) {
        float v = e[c];
        s = fmaf(v, v, s);
    }
#pragma unroll
    for (int o = 16; o; o >>= 1) s += __shfl_xor_sync(0xffffffffu, s, o);
    if (lane == 0) g_enorm[row] = s;
}

// ---------------- persistent GEMM + argmin ----------------
__global__ void __launch_bounds__(256, 1) vq_gemm_kernel() {
    extern __shared__ __align__(1024) char smem[];
    const int tid = threadIdx.x;

#if defined(__CUDA_ARCH_FEAT_SM103_ALL)
    const uint32_t sb = smem_u32(smem);

    if (tid < 32) {
        TCGEN05_ALLOC(sb, 512);
        TCGEN05_RELINQUISH();
    }
    if (tid == 0) {
#pragma unroll
        for (int i = 0; i < 6; i++) MBARRIER_INIT(sb + TC_MBAR_OFF + i * 8, 1);
    }
    __syncthreads();
    uint32_t tmem_base;
    asm volatile("ld.shared.b32 %0, [%1];" : "=r"(tmem_base) : "r"(sb));

    auto issue_load = [&](int lc2) {
        int tt = blockIdx.x + GEMM_GRID * (lc2 >> 3);
        if (tt >= N_TILES) return;
        int s2 = lc2 & 7, b2 = lc2 % 3;
        uint32_t dst = sb + TC_STAGE0 + (uint32_t)b2 * TC_STAGE_BYTES;
        const char* srcA = (const char*)g_za + (size_t)((tt >> 5) * 8 + s2) * 32768u;
        const char* srcB = (const char*)g_zb + (size_t)((tt & 31) * 8 + s2) * 32768u;
        uint32_t mb = sb + TC_MBAR_OFF + b2 * 8;
        MBARRIER_EXPECT_TX(mb, 65536u);
        CP_BULK(dst, srcA, 32768u, mb);
        CP_BULK(dst + 32768u, srcB, 32768u, mb);
    };

    uint32_t lph[3] = {0, 0, 0};
    uint32_t mph[3] = {0, 0, 0};
    if (tid == 0) {
        issue_load(0);
        issue_load(1);
    }
    int lc = 0;

    for (int t = blockIdx.x; t < N_TILES; t += GEMM_GRID) {
        const int nt = t & 31;
        ((float*)(smem + TC_EN_OFF))[tid] = g_enorm[nt * 256 + tid];

        for (int s = 0; s < 8; s++, lc++) {
            if (tid == 0) {
                const int buf = lc % 3;
                MBARRIER_WAIT_PARITY(sb + TC_MBAR_OFF + buf * 8, lph[buf]);
                lph[buf] ^= 1;

                uint32_t abase = sb + TC_STAGE0 + (uint32_t)buf * TC_STAGE_BYTES;
                unsigned long long ad0 = make_desc(abase);
                unsigned long long ad1 = make_desc(abase + 16384u);
                unsigned long long bd = make_desc(abase + 32768u);
#pragma unroll
                for (int p = 0; p < 3; p++) {
                    const int ao = (p == 2) ? 4 : 0;
                    const int bo = (p == 1) ? 4 : 0;
#pragma unroll
                    for (int ks = 0; ks < 2; ks++) {
                        uint32_t en = (s == 0 && p == 0 && ks == 0) ? 0u : 1u;
                        mma_f16_ss(tmem_base, ad0 + ao + ks * 2, bd + bo + ks * 2, en);
                        mma_f16_ss(tmem_base + 256, ad1 + ao + ks * 2, bd + bo + ks * 2, en);
                    }
                }
                TCGEN05_COMMIT(sb + TC_MBAR_OFF + 24 + buf * 8);

                if (lc >= 1) {
                    const int pb = (lc - 1) % 3;
                    MBARRIER_WAIT_PARITY(sb + TC_MBAR_OFF + 24 + pb * 8, mph[pb]);
                    mph[pb] ^= 1;
                }
                issue_load(lc + 2);
            }
        }

        // gate epilogue on this tile's last commit (same phase re-waited
        // without toggle; the in-loop wait next tile consumes it cheaply)
        if (tid == 0) {
            const int lb = (lc - 1) % 3;
            MBARRIER_WAIT_PARITY(sb + TC_MBAR_OFF + 24 + lb * 8, mph[lb]);
        }
        __syncthreads();
        TCGEN05_FENCE_AFTER();

        // epilogue: warp w -> row-group (w&3), col-half (w>>2); both D tiles
        {
            const int w = tid >> 5;
            const int sub = w & 3;
            const int half = w >> 2;
            const int lane = tid & 31;
            const float* en = (const float*)(smem + TC_EN_OFF);
            const int mt = t >> 5;
#pragma unroll
            for (int h = 0; h < 2; h++) {
                const int mrow = mt * 256 + h * 128 + sub * 32 + lane;
                float dmin = 3.4e38f;
                int besti = 0;
#pragma unroll
                for (int c0 = 0; c0 < 128; c0 += 32) {
                    uint32_t r[32];
                    TCGEN05_LD_32X32B_X32(r, tmem_base + h * 256 + half * 128 + c0);
                    TCGEN05_WAIT_LD();
#pragma unroll
                    for (int j = 0; j < 32; j++) {
                        int nl = half * 128 + c0 + j;
                        float d = en[nl] - 2.0f * __uint_as_float(r[j]);
                        if (d < dmin) { dmin = d; besti = nl; }
                    }
                }
                unsigned long long key =
                    ((unsigned long long)fkey(dmin) << 32) | (unsigned)(nt * 256 + besti);
                atomicMin(&g_best[mrow], key);
            }
        }
        TCGEN05_FENCE_BEFORE();
        __syncthreads();
    }

    if (tid < 32) TCGEN05_DEALLOC(tmem_base, 512);

#else
    // ===== fallback (compile-only on the PTX pass; never executes on sm_103a) =====
    const int bm = blockIdx.y * FB_MT;
    const int bn = blockIdx.x * FB_NT;
    const uint32_t sb = smem_u32(smem);
    if (tid < FB_NT) ((float*)(smem + FB_EN))[tid] = g_enorm[bn + tid];

    const int w = tid >> 5;
    const int lane = tid & 31;
    const int g = lane >> 2;
    const int t4 = lane & 3;
    const int wm = w >> 2;
    const int wn = w & 3;

    float acc[4][4][4];
#pragma unroll
    for (int i = 0; i < 4; i++)
#pragma unroll
        for (int j = 0; j < 4; j++)
#pragma unroll
            for (int c = 0; c < 4; c++) acc[i][j][c] = 0.f;

    auto load_stage = [&](int s) {
        const int p = s >> 3;
        const int k0 = (s & 7) * 32;
        const __half* asrc = (p == 2) ? g_zl : g_zh;
        const __half* bsrc = (p == 1) ? g_el : g_eh;
        const uint32_t abase = sb + FB_STAGE0 + (uint32_t)(s & (FB_STAGES - 1)) * FB_STAGE_BYTES;
        const uint32_t bbase = abase + FB_A_TILE;
#pragma unroll
        for (int it = 0; it < 2; it++) {
            int idx = tid + it * 256;
            int row = idx >> 2, c2 = idx & 3;
            cp16(abase + (uint32_t)(row * FB_LDAB + c2 * 16),
                 asrc + (size_t)(bm + row) * KDIM + k0 + c2 * 8);
        }
#pragma unroll
        for (int it = 0; it < 2; it++) {
            int idx = tid + it * 256;
            int row = idx >> 2, c2 = idx & 3;
            cp16(bbase + (uint32_t)(row * FB_LDAB + c2 * 16),
                 bsrc + (size_t)(bn + row) * KDIM + k0 + c2 * 8);
        }
        cp_commit();
    };

    load_stage(0);
    load_stage(1);
    load_stage(2);

    for (int s = 0; s < FB_CHUNKS; s++) {
        if (s < FB_CHUNKS - 2) cp_wait2();
        else if (s == FB_CHUNKS - 2) cp_wait1();
        else cp_wait0();
        __syncthreads();
        if (s + 3 < FB_CHUNKS) load_stage(s + 3);

        const uint32_t abase = sb + FB_STAGE0 + (uint32_t)(s & (FB_STAGES - 1)) * FB_STAGE_BYTES;
        const uint32_t bbase = abase + FB_A_TILE;
        const uint32_t arow = abase + (uint32_t)((wm * 64 + g) * FB_LDAB + t4 * 4);
        const uint32_t brow = bbase + (uint32_t)((wn * 32 + g) * FB_LDAB + t4 * 4);

#pragma unroll
        for (int ks = 0; ks < 2; ks++) {
            uint32_t a[4][4];
#pragma unroll
            for (int i = 0; i < 4; i++) {
                uint32_t ab = arow + (uint32_t)(i * 16 * FB_LDAB + ks * 32);
                asm volatile("ld.shared.b32 %0, [%1];" : "=r"(a[i][0]) : "r"(ab));
                asm volatile("ld.shared.b32 %0, [%1];" : "=r"(a[i][1]) : "r"(ab + 8 * FB_LDAB));
                asm volatile("ld.shared.b32 %0, [%1];" : "=r"(a[i][2]) : "r"(ab + 16));
                asm volatile("ld.shared.b32 %0, [%1];" : "=r"(a[i][3]) : "r"(ab + 8 * FB_LDAB + 16));
            }
            uint32_t b[4][2];
#pragma unroll
            for (int j = 0; j < 4; j++) {
                uint32_t bb = brow + (uint32_t)(j * 8 * FB_LDAB + ks * 32);
                asm volatile("ld.shared.b32 %0, [%1];" : "=r"(b[j][0]) : "r"(bb));
                asm volatile("ld.shared.b32 %0, [%1];" : "=r"(b[j][1]) : "r"(bb + 16));
            }
#pragma unroll
            for (int i = 0; i < 4; i++)
#pragma unroll
                for (int j = 0; j < 4; j++) {
                    asm("mma.sync.aligned.m16n8k16.row.col.f32.f16.f16.f32 "
                        "{%0,%1,%2,%3},{%4,%5,%6,%7},{%8,%9},{%0,%1,%2,%3};"
                        : "+f"(acc[i][j][0]), "+f"(acc[i][j][1]),
                          "+f"(acc[i][j][2]), "+f"(acc[i][j][3])
                        : "r"(a[i][0]), "r"(a[i][1]), "r"(a[i][2]), "r"(a[i][3]),
                          "r"(b[j][0]), "r"(b[j][1]));
                }
        }
    }

    const float* en = (const float*)(smem + FB_EN);
#pragma unroll
    for (int i = 0; i < 4; i++) {
        const int r0 = bm + wm * 64 + i * 16 + g;
        unsigned long long k0 = ~0ull, k1 = ~0ull;
#pragma unroll
        for (int j = 0; j < 4; j++) {
            int n0 = wn * 32 + j * 8 + 2 * t4;
            float d;
            unsigned long long key;
            d = en[n0] - 2.f * acc[i][j][0];
            key = ((unsigned long long)fkey(d) << 32) | (unsigned)(bn + n0);
            k0 = umin64(k0, key);
            d = en[n0 + 1] - 2.f * acc[i][j][1];
            key = ((unsigned long long)fkey(d) << 32) | (unsigned)(bn + n0 + 1);
            k0 = umin64(k0, key);
            d = en[n0] - 2.f * acc[i][j][2];
            key = ((unsigned long long)fkey(d) << 32) | (unsigned)(bn + n0);
            k1 = umin64(k1, key);
            d = en[n0 + 1] - 2.f * acc[i][j][3];
            key = ((unsigned long long)fkey(d) << 32) | (unsigned)(bn + n0 + 1);
            k1 = umin64(k1, key);
        }
        k0 = umin64(k0, __shfl_xor_sync(0xffffffffu, k0, 1));
        k0 = umin64(k0, __shfl_xor_sync(0xffffffffu, k0, 2));
        k1 = umin64(k1, __shfl_xor_sync(0xffffffffu, k1, 1));
        k1 = umin64(k1, __shfl_xor_sync(0xffffffffu, k1, 2));
        if (t4 == 0) {
            atomicMin(&g_best[r0], k0);
            atomicMin(&g_best[r0 + 8], k1);
        }
    }
#endif
}

// ---------------- gather + loss ----------------
__global__ void gather_kernel(const float* __restrict__ z,
                              const float* __restrict__ emb,
                              float* __restrict__ out, int has_extra) {
    __shared__ float sw[8];
    const int tid = threadIdx.x;
    const int r = tid >> 6;
    const int c = tid & 63;
    const int row = blockIdx.x * 4 + r;
    unsigned long long key = g_best[row];
    int idx = (int)(key & 0xFFFFFFFFull);

    float4 q = ((const float4*)emb)[(size_t)idx * 64 + c];
    float4 zv = ((const float4*)z)[(size_t)row * 64 + c];
    ((float4*)out)[(size_t)row * 64 + c] = q;

    float dx = q.x - zv.x, dy = q.y - zv.y, dz = q.z - zv.z, dw = q.w - zv.w;
    float s = dx * dx + dy * dy + dz * dz + dw * dw;
#pragma unroll
    for (int o = 16; o; o >>= 1) s += __shfl_xor_sync(0xffffffffu, s, o);
    if ((tid & 31) == 0) sw[tid >> 5] = s;
    __syncthreads();
    if (c == 0) {
        float tot = sw[r * 2] + sw[r * 2 + 1];
        g_partial[row] = tot;
        if (has_extra) out[Q_ELEMS + 1 + row] = (float)idx;
    }
}

__global__ void finalize_kernel(float* __restrict__ out, int has_extra) {
    if (!has_extra) return;
    __shared__ float sh[256];
    int tid = threadIdx.x;
    float s = 0.f;
    for (int i = tid; i < M_ROWS; i += 256) s += g_partial[i];
    sh[tid] = s;
    __syncthreads();
#pragma unroll
    for (int o = 128; o; o >>= 1) {
        if (tid < o) sh[tid] += sh[tid + o];
        __syncthreads();
    }
    if (tid == 0) out[Q_ELEMS] = 1.25f * sh[0] / (float)Q_ELEMS;
}

// ---------------- launcher ----------------
extern "C" void kernel_launch(void* const* d_in, const int* in_sizes, int n_in,
                              void* d_out, int out_size) {
    const float* z;
    const float* emb;
    if (in_sizes[0] == M_ROWS * KDIM) {
        z = (const float*)d_in[0];
        emb = (const float*)d_in[1];
    } else {
        z = (const float*)d_in[1];
        emb = (const float*)d_in[0];
    }
    float* out = (float*)d_out;
    int has_extra = (out_size >= Q_ELEMS + 1 + M_ROWS) ? 1 : 0;

    cudaFuncSetAttribute(vq_gemm_kernel,
                         cudaFuncAttributeMaxDynamicSharedMemorySize, TC_TOTAL);

    pack_z_kernel<<<M_ROWS * 32 / 256, 256>>>(z);     // also inits g_best
    pack_e_kernel<<<N_CODES * 32 / 256, 256>>>(emb);
    enorm_kernel<<<N_CODES / 8, 256>>>(emb);

    vq_gemm_kernel<<<GEMM_GRID, 256, TC_TOTAL>>>();

    gather_kernel<<<M_ROWS / 4, 256>>>(z, emb, out, has_extra);
    finalize_kernel<<<1, 256>>>(out, has_extra);
}